// round 11
// baseline (speedup 1.0000x reference)
#include <cuda_runtime.h>
#include <stdint.h>

#define DIM   2048
#define NE    64
#define TOPK  8
#define BT    256            // tokens per CTA
#define NTHR  128
#define KC    32             // k per smem chunk
#define NCHK  (DIM / KC)     // 64
#define XROW  36             // x smem row floats (KC + 4 pad; 144B, 16B-aligned)
#define XB    (BT * XROW)    // 9216 floats per x buffer
#define WB    (KC * NE)      // 2048 floats per w buffer
#define SSTR  66
#define LOG2E 1.4426950408889634f

// Transposed weights [k][expert] (natural order -> adjacent experts pair
// into f32x2). 512 KB, L2-resident.
__device__ float4 g_wt4[DIM * (NE / 4)];
__device__ int    g_hist[NE];
__device__ int    g_cnt;

// ---------------- helpers ----------------
__device__ __forceinline__ void ffma2(unsigned long long &d,
                                      unsigned long long a,
                                      unsigned long long b) {
    asm("fma.rn.f32x2 %0, %1, %2, %0;" : "+l"(d) : "l"(a), "l"(b));
}
__device__ __forceinline__ unsigned long long dup2(float w) {
    unsigned long long r;
    asm("mov.b64 %0, {%1, %1};" : "=l"(r) : "f"(w));
    return r;
}
__device__ __forceinline__ float2 ull_as_f2(unsigned long long v) {
    float2 r;
    asm("mov.b64 {%0, %1}, %2;" : "=f"(r.x), "=f"(r.y) : "l"(v));
    return r;
}
__device__ __forceinline__ void cp16(uint32_t dst_smem, const void* src) {
    asm volatile("cp.async.ca.shared.global [%0], [%1], 16;"
                 :: "r"(dst_smem), "l"(src));
}
__device__ __forceinline__ void cp_commit() {
    asm volatile("cp.async.commit_group;");
}
__device__ __forceinline__ void cp_wait0() {
    asm volatile("cp.async.wait_group 0;" ::: "memory");
}

// ============================================================
// Prep: transpose gate_weight [64][2048] -> g_wt4 [2048][16xf4]
// (slot p = experts 4p..4p+3, natural order).
// ============================================================
__global__ void prep_kernel(const float* __restrict__ gw) {
    __shared__ float ts[64][68];
    const int t = threadIdx.x, blk = blockIdx.x;
    #pragma unroll
    for (int i = 0; i < 4; i++) {
        int idx = t + i * 256;
        int e = idx >> 4, q = idx & 15;
        float4 f = ((const float4*)gw)[e * 512 + blk * 16 + q];
        ts[e][q * 4 + 0] = f.x; ts[e][q * 4 + 1] = f.y;
        ts[e][q * 4 + 2] = f.z; ts[e][q * 4 + 3] = f.w;
    }
    __syncthreads();
    #pragma unroll
    for (int i = 0; i < 4; i++) {
        int idx = t + i * 256;
        int k = idx >> 4, p = idx & 15;
        g_wt4[(blk * 64 + k) * 16 + p] =
            make_float4(ts[p * 4 + 0][k], ts[p * 4 + 1][k],
                        ts[p * 4 + 2][k], ts[p * 4 + 3][k]);
    }
    if (blk == 0 && t < NE) g_hist[t] = 0;
    if (blk == 0 && t == 0) g_cnt = 0;
}

// ============================================================
// Fused gate kernel. CTA: 256 tok x 64 exp, 128 threads, grid 128.
// Thread tile 8 tok x 16 exp; experts packed in f32x2 (w loads are
// the FFMA2 operand directly), x via LDS.32 (1 wf/instr) + dup2.
// x staged via cp.async untransposed ([tok][k], 144B rows).
// Per-(token,expert): sequential fp32 FMA chain, k ascending —
// bitwise identical to R1/R6-R10.
// ============================================================
__global__ void __launch_bounds__(NTHR, 1)
gate_kernel(const float* __restrict__ x,
            const float* __restrict__ bias_in,
            const float* __restrict__ usage_in,
            float* __restrict__ out, int T, float inv_total) {
    extern __shared__ float sm[];
    float* xsm    = sm;                        // [2][256][36] = 18432 f
    float* wsm    = sm + 2 * XB;               // [2][KC][64]  = 4096 f
    float* sc     = sm;                        // [256][66] — aliases bufs
    float* bias_s = sm + 2 * XB + 2 * WB;      // [64]
    int*   hist_s = (int*)(bias_s + NE);       // [64]
    int*   flag_s = hist_s + NE;

    const int tid = threadIdx.x;
    const int tg  = tid >> 2;                  // token group: tokens tg*8..+7
    const int eg  = tid & 3;                   // expert group: exps eg*16..+15
    const long long tb = (long long)blockIdx.x * BT;

    if (tid < NE) { hist_s[tid] = 0; bias_s[tid] = bias_in[tid]; }

    const uint32_t xsm_u32 = (uint32_t)__cvta_generic_to_shared(xsm);
    const uint32_t wsm_u32 = (uint32_t)__cvta_generic_to_shared(wsm);
    const float* xg0 = x + (tb + tid) * (long long)DIM;        // staging tok A
    const float* xg1 = x + (tb + tid + 128) * (long long)DIM;  // staging tok B

    // ---- stage chunk 0 (pure cp.async, no transpose) ----
    {
        const uint32_t xd0 = xsm_u32 + tid * 144;
        const uint32_t xd1 = xsm_u32 + (tid + 128) * 144;
        #pragma unroll
        for (int j = 0; j < 8; j++) {
            cp16(xd0 + j * 16, xg0 + j * 4);
            cp16(xd1 + j * 16, xg1 + j * 4);
        }
        #pragma unroll
        for (int i = 0; i < 4; i++)
            cp16(wsm_u32 + (tid * 4 + i) * 16, &g_wt4[tid * 4 + i]);
        cp_commit();
    }

    unsigned long long acc[8][8];   // [token][expert-pair]
    #pragma unroll
    for (int t = 0; t < 8; t++)
        #pragma unroll
        for (int e = 0; e < 8; e++) acc[t][e] = 0ull;

    cp_wait0();
    __syncthreads();

    for (int ch = 0; ch < NCHK; ch++) {
        const int buf = ch & 1;

        // stage next chunk (cp.async into other buffer)
        if (ch + 1 < NCHK) {
            const uint32_t xoff = (buf ^ 1) * (XB * 4);
            const uint32_t xd0 = xsm_u32 + xoff + tid * 144;
            const uint32_t xd1 = xsm_u32 + xoff + (tid + 128) * 144;
            const float* xs0 = xg0 + (ch + 1) * KC;
            const float* xs1 = xg1 + (ch + 1) * KC;
            #pragma unroll
            for (int j = 0; j < 8; j++) {
                cp16(xd0 + j * 16, xs0 + j * 4);
                cp16(xd1 + j * 16, xs1 + j * 4);
            }
            const uint32_t wdst = wsm_u32 + (buf ^ 1) * (WB * 4);
            #pragma unroll
            for (int i = 0; i < 4; i++)
                cp16(wdst + (tid * 4 + i) * 16,
                     &g_wt4[(ch + 1) * 512 + tid * 4 + i]);
            cp_commit();
        }

        const float* xb = xsm + buf * XB + tg * 8 * XROW;  // 8 token rows
        const float* wb = wsm + buf * WB + eg * 16;        // 16 experts

        // software-pipelined inner loop (1-k operand double buffer)
        float xv[8]; ulonglong2 wv[4];
        #pragma unroll
        for (int t = 0; t < 8; t++) xv[t] = xb[t * XROW];
        #pragma unroll
        for (int p = 0; p < 4; p++)
            wv[p] = *(const ulonglong2*)(wb + p * 4);

        #pragma unroll
        for (int k = 0; k < KC; k++) {
            float xn[8]; ulonglong2 wn[4];
            if (k + 1 < KC) {
                #pragma unroll
                for (int t = 0; t < 8; t++) xn[t] = xb[t * XROW + k + 1];
                #pragma unroll
                for (int p = 0; p < 4; p++)
                    wn[p] = *(const ulonglong2*)(wb + (k + 1) * NE + p * 4);
            }
            unsigned long long xd[8];
            #pragma unroll
            for (int t = 0; t < 8; t++) xd[t] = dup2(xv[t]);
            #pragma unroll
            for (int p = 0; p < 4; p++) {
                #pragma unroll
                for (int t = 0; t < 8; t++) {
                    ffma2(acc[t][2 * p],     xd[t], wv[p].x);
                    ffma2(acc[t][2 * p + 1], xd[t], wv[p].y);
                }
            }
            if (k + 1 < KC) {
                #pragma unroll
                for (int t = 0; t < 8; t++) xv[t] = xn[t];
                #pragma unroll
                for (int p = 0; p < 4; p++) wv[p] = wn[p];
            }
        }

        if (ch + 1 < NCHK) cp_wait0();
        __syncthreads();
    }

    // ---- accumulators -> smem scores (pipeline bufs are dead) ----
    #pragma unroll
    for (int t = 0; t < 8; t++) {
        #pragma unroll
        for (int e = 0; e < 8; e++) {
            float2 v = ull_as_f2(acc[t][e]);
            *(float2*)(sc + (tg * 8 + t) * SSTR + eg * 16 + 2 * e) = v;
        }
    }
    __syncthreads();

    // ---- per-token epilogue: softmax + top-8 (2 tokens/thread) ----
    for (int tt = tid; tt < BT; tt += NTHR) {
        float* row = sc + tt * SSTR;
        float m = -3.4e38f;
        #pragma unroll
        for (int e = 0; e < NE; e++) {
            float v = row[e] + bias_s[e];
            row[e] = v;
            m = fmaxf(m, v);
        }
        float z = 0.0f;
        #pragma unroll
        for (int e = 0; e < NE; e++)
            z += exp2f((row[e] - m) * LOG2E);
        float invz = 1.0f / z;

        unsigned long long msk = 0ull;
        float tw[TOPK]; int ti[TOPK];
        float ts = 0.0f;
        #pragma unroll 1
        for (int it = 0; it < TOPK; it++) {
            float bv = -3.4e38f; int bi = 0;
            #pragma unroll
            for (int e = 0; e < NE; e++) {
                float v = row[e];
                bool ok = (((msk >> e) & 1ull) == 0ull) && (v > bv);
                if (ok) { bv = v; bi = e; }
            }
            msk |= 1ull << bi;
            float p = exp2f((bv - m) * LOG2E) * invz;
            ts += p; tw[it] = p; ti[it] = bi;
        }
        float inv = 1.0f / (ts + 1e-8f);

        const long long tok = tb + tt;
        float* ow = out + tok * TOPK;
        float* oi = out + (long long)T * TOPK + tok * TOPK;
        *(float4*)(ow)     = make_float4(tw[0]*inv, tw[1]*inv, tw[2]*inv, tw[3]*inv);
        *(float4*)(ow + 4) = make_float4(tw[4]*inv, tw[5]*inv, tw[6]*inv, tw[7]*inv);
        *(float4*)(oi)     = make_float4((float)ti[0], (float)ti[1], (float)ti[2], (float)ti[3]);
        *(float4*)(oi + 4) = make_float4((float)ti[4], (float)ti[5], (float)ti[6], (float)ti[7]);
        #pragma unroll
        for (int k = 0; k < TOPK; k++) atomicAdd(&hist_s[ti[k]], 1);
    }
    __syncthreads();

    if (tid < NE) {
        atomicAdd(&g_hist[tid], hist_s[tid]);
        __threadfence();
    }
    __syncthreads();

    // ---- last-CTA finalize ----
    if (tid == 0) {
        int t = atomicAdd(&g_cnt, 1);
        *flag_s = (t == (int)gridDim.x - 1) ? 1 : 0;
    }
    __syncthreads();
    if (*flag_s) {
        __threadfence();
        if (tid < NE) {
            int cnt = atomicAdd(&g_hist[tid], 0);
            float u = (float)cnt * inv_total;
            float* out_bias  = out + 2LL * T * TOPK;
            float* out_usage = out_bias + NE;
            out_bias[tid]  = bias_in[tid] - 0.01f * (u - 1.0f / (float)NE);
            out_usage[tid] = 0.9f * usage_in[tid] + 0.1f * u;
        }
        if (tid == 0) atomicExch(&g_cnt, 0);
    }
}

// ============================================================
extern "C" void kernel_launch(void* const* d_in, const int* in_sizes, int n_in,
                              void* d_out, int out_size) {
    const float* x     = (const float*)d_in[0];   // [4, 8192, 2048]
    const float* gw    = (const float*)d_in[1];   // [64, 2048]
    const float* bias  = (const float*)d_in[2];   // [64]
    const float* usage = (const float*)d_in[3];   // [64]

    const int T = in_sizes[0] / DIM;              // 32768
    float* out = (float*)d_out;

    const int smem_bytes = (2 * XB + 2 * WB + NE) * 4 + NE * 4 + 16;
    cudaFuncSetAttribute(gate_kernel,
                         cudaFuncAttributeMaxDynamicSharedMemorySize, smem_bytes);

    prep_kernel<<<32, 256>>>(gw);
    gate_kernel<<<T / BT, NTHR, smem_bytes>>>(x, bias, usage, out, T,
                                              1.0f / (float)(T * TOPK));
}

// round 12
// speedup vs baseline: 1.4200x; 1.4200x over previous
#include <cuda_runtime.h>
#include <stdint.h>

#define DIM   2048
#define NE    64
#define TOPK  8
#define BT    128            // tokens per CTA
#define NTHR  128
#define KC    16             // k per smem chunk
#define NCHK  (DIM / KC)     // 128
#define XB    (KC * BT)      // 2048 floats per x buffer
#define WB    (KC * NE)      // 1024 floats per w buffer
#define SSTR  66
#define SCFL  (BT * SSTR)    // 8448 floats (score region, aliases pipeline)
#define LOG2E 1.4426950408889634f

// Transposed + bank-permuted weights [k][slot] as float4. 512 KB, L2-resident.
// Slot p of a k-row: p<8 -> experts p*8+0..3 ; p>=8 -> experts (p-8)*8+4..7.
// Thread eg reads its 8 experts as two conflict-free LDS.128.
__device__ float4 g_wt4[DIM * (NE / 4)];
__device__ int    g_hist[NE];
__device__ int    g_cnt;

// ---------------- helpers ----------------
__device__ __forceinline__ void ffma2(unsigned long long &d,
                                      unsigned long long a,
                                      unsigned long long b) {
    asm("fma.rn.f32x2 %0, %1, %2, %0;" : "+l"(d) : "l"(a), "l"(b));
}
__device__ __forceinline__ unsigned long long dup2(float w) {
    unsigned long long r;
    asm("mov.b64 %0, {%1, %1};" : "=l"(r) : "f"(w));
    return r;
}
__device__ __forceinline__ float2 ull_as_f2(unsigned long long v) {
    float2 r;
    asm("mov.b64 {%0, %1}, %2;" : "=f"(r.x), "=f"(r.y) : "l"(v));
    return r;
}
__device__ __forceinline__ void cp16(uint32_t dst_smem, const void* src) {
    asm volatile("cp.async.ca.shared.global [%0], [%1], 16;"
                 :: "r"(dst_smem), "l"(src));
}
__device__ __forceinline__ void cp_commit() {
    asm volatile("cp.async.commit_group;");
}
__device__ __forceinline__ void cp_wait0() {
    asm volatile("cp.async.wait_group 0;" ::: "memory");
}

// ============================================================
// Prep: transpose gate_weight [64][2048] -> g_wt4 [2048][16 slots]
// with the conflict-free slot permutation.
// ============================================================
__global__ void prep_kernel(const float* __restrict__ gw) {
    __shared__ float ts[64][68];
    const int t = threadIdx.x, blk = blockIdx.x;
    #pragma unroll
    for (int i = 0; i < 4; i++) {
        int idx = t + i * 256;
        int e = idx >> 4, q = idx & 15;
        float4 f = ((const float4*)gw)[e * 512 + blk * 16 + q];
        ts[e][q * 4 + 0] = f.x; ts[e][q * 4 + 1] = f.y;
        ts[e][q * 4 + 2] = f.z; ts[e][q * 4 + 3] = f.w;
    }
    __syncthreads();
    #pragma unroll
    for (int i = 0; i < 4; i++) {
        int idx = t + i * 256;
        int k = idx >> 4, p = idx & 15;
        int base = (p < 8) ? p * 8 : (p - 8) * 8 + 4;
        g_wt4[(blk * 64 + k) * 16 + p] =
            make_float4(ts[base + 0][k], ts[base + 1][k],
                        ts[base + 2][k], ts[base + 3][k]);
    }
    if (blk == 0 && t < NE) g_hist[t] = 0;
    if (blk == 0 && t == 0) g_cnt = 0;
}

// one k-step: 8 dup MOVs (alu pipe) + 32 FFMA2 (fma pipe)
#define COMPUTE_K(XA, XC, W0, W1)                                  \
    do {                                                           \
        unsigned long long wd0 = dup2((W0).x), wd1 = dup2((W0).y); \
        unsigned long long wd2 = dup2((W0).z), wd3 = dup2((W0).w); \
        unsigned long long wd4 = dup2((W1).x), wd5 = dup2((W1).y); \
        unsigned long long wd6 = dup2((W1).z), wd7 = dup2((W1).w); \
        ffma2(acc[0][0], (XA).x, wd0); ffma2(acc[1][0], (XA).y, wd0); \
        ffma2(acc[2][0], (XC).x, wd0); ffma2(acc[3][0], (XC).y, wd0); \
        ffma2(acc[0][1], (XA).x, wd1); ffma2(acc[1][1], (XA).y, wd1); \
        ffma2(acc[2][1], (XC).x, wd1); ffma2(acc[3][1], (XC).y, wd1); \
        ffma2(acc[0][2], (XA).x, wd2); ffma2(acc[1][2], (XA).y, wd2); \
        ffma2(acc[2][2], (XC).x, wd2); ffma2(acc[3][2], (XC).y, wd2); \
        ffma2(acc[0][3], (XA).x, wd3); ffma2(acc[1][3], (XA).y, wd3); \
        ffma2(acc[2][3], (XC).x, wd3); ffma2(acc[3][3], (XC).y, wd3); \
        ffma2(acc[0][4], (XA).x, wd4); ffma2(acc[1][4], (XA).y, wd4); \
        ffma2(acc[2][4], (XC).x, wd4); ffma2(acc[3][4], (XC).y, wd4); \
        ffma2(acc[0][5], (XA).x, wd5); ffma2(acc[1][5], (XA).y, wd5); \
        ffma2(acc[2][5], (XC).x, wd5); ffma2(acc[3][5], (XC).y, wd5); \
        ffma2(acc[0][6], (XA).x, wd6); ffma2(acc[1][6], (XA).y, wd6); \
        ffma2(acc[2][6], (XC).x, wd6); ffma2(acc[3][6], (XC).y, wd6); \
        ffma2(acc[0][7], (XA).x, wd7); ffma2(acc[1][7], (XA).y, wd7); \
        ffma2(acc[2][7], (XC).x, wd7); ffma2(acc[3][7], (XC).y, wd7); \
    } while (0)

// ============================================================
// Fused gate kernel. CTA: 128 tok x 64 exp, 128 threads; grid 256
// -> 2 independent CTAs per SM (decoupled barriers; all 148 SMs).
// Thread tile 8 tok x 8 exp. Per-(token,expert): sequential fp32
// FMA chain, k ascending — bitwise identical to R1/R6-R11.
// ============================================================
__global__ void __launch_bounds__(NTHR, 2)
gate_kernel(const float* __restrict__ x,
            const float* __restrict__ bias_in,
            const float* __restrict__ usage_in,
            float* __restrict__ out, int T, float inv_total) {
    extern __shared__ float sm[];
    float* xsm    = sm;                        // [2][KC][128] = 4096 f
    float* wsm    = sm + 2 * XB;               // [2][KC][64]  = 2048 f
    float* sc     = sm;                        // [128][66] — aliases bufs
    float* bias_s = sm + SCFL;                 // [64]
    int*   hist_s = (int*)(bias_s + NE);       // [64]
    int*   flag_s = hist_s + NE;

    const int tid = threadIdx.x;
    const int tg  = tid >> 3;                  // token group (8 tokens), 0..15
    const int eg  = tid & 7;                   // expert group (8 experts)
    const long long tb = (long long)blockIdx.x * BT;

    if (tid < NE) { hist_s[tid] = 0; bias_s[tid] = bias_in[tid]; }

    const float* xg = x + (tb + tid) * (long long)DIM;  // staging token = tid
    const uint32_t wsm_u32 = (uint32_t)__cvta_generic_to_shared(wsm);

    // ---- stage chunk 0 ----
    {
        cp16(wsm_u32 + tid * 32,      &g_wt4[tid * 2]);
        cp16(wsm_u32 + tid * 32 + 16, &g_wt4[tid * 2 + 1]);
        cp_commit();
        #pragma unroll
        for (int i = 0; i < 4; i++) {
            float4 v = *(const float4*)(xg + i * 4);
            xsm[(i * 4 + 0) * BT + tid] = v.x;
            xsm[(i * 4 + 1) * BT + tid] = v.y;
            xsm[(i * 4 + 2) * BT + tid] = v.z;
            xsm[(i * 4 + 3) * BT + tid] = v.w;
        }
    }

    unsigned long long acc[4][8];
    #pragma unroll
    for (int tp = 0; tp < 4; tp++)
        #pragma unroll
        for (int e = 0; e < 8; e++) acc[tp][e] = 0ull;

    cp_wait0();
    __syncthreads();

    for (int ch = 0; ch < NCHK; ch++) {
        const int buf = ch & 1;

        // next-chunk producers: w cp.async straight to smem, x to regs
        float4 xn0, xn1, xn2, xn3;
        if (ch + 1 < NCHK) {
            const uint32_t wdst = wsm_u32 + (buf ^ 1) * (WB * 4);
            cp16(wdst + tid * 32,      &g_wt4[(ch + 1) * 256 + tid * 2]);
            cp16(wdst + tid * 32 + 16, &g_wt4[(ch + 1) * 256 + tid * 2 + 1]);
            cp_commit();
            const float* xp = xg + (ch + 1) * KC;
            xn0 = *(const float4*)(xp);
            xn1 = *(const float4*)(xp + 4);
            xn2 = *(const float4*)(xp + 8);
            xn3 = *(const float4*)(xp + 12);
        }

        const float* xb = xsm + buf * XB + tg * 8;
        const float* wb = wsm + buf * WB + eg * 4;   // permuted, conflict-free

        // software-pipelined inner loop: 1-k operand double buffer
        ulonglong2 xa = *(const ulonglong2*)(xb);
        ulonglong2 xc = *(const ulonglong2*)(xb + 4);
        float4 w0 = *(const float4*)(wb);
        float4 w1 = *(const float4*)(wb + 32);

        #pragma unroll
        for (int k = 0; k < KC - 1; k++) {
            ulonglong2 xa2 = *(const ulonglong2*)(xb + (k + 1) * BT);
            ulonglong2 xc2 = *(const ulonglong2*)(xb + (k + 1) * BT + 4);
            float4 v0 = *(const float4*)(wb + (k + 1) * NE);
            float4 v1 = *(const float4*)(wb + (k + 1) * NE + 32);
            COMPUTE_K(xa, xc, w0, w1);
            xa = xa2; xc = xc2; w0 = v0; w1 = v1;
        }
        COMPUTE_K(xa, xc, w0, w1);   // peeled last k

        // stage next x chunk into the other buffer
        if (ch + 1 < NCHK) {
            float* xd = xsm + (buf ^ 1) * XB;
            float4 vv[4] = {xn0, xn1, xn2, xn3};
            #pragma unroll
            for (int i = 0; i < 4; i++) {
                xd[(i * 4 + 0) * BT + tid] = vv[i].x;
                xd[(i * 4 + 1) * BT + tid] = vv[i].y;
                xd[(i * 4 + 2) * BT + tid] = vv[i].z;
                xd[(i * 4 + 3) * BT + tid] = vv[i].w;
            }
            cp_wait0();
        }
        __syncthreads();
    }

    // ---- accumulators -> smem scores (pipeline bufs are dead) ----
    #pragma unroll
    for (int tp = 0; tp < 4; tp++) {
        #pragma unroll
        for (int e = 0; e < 8; e++) {
            float2 v = ull_as_f2(acc[tp][e]);
            sc[(tg * 8 + tp * 2) * SSTR + eg * 8 + e]     = v.x;
            sc[(tg * 8 + tp * 2 + 1) * SSTR + eg * 8 + e] = v.y;
        }
    }
    __syncthreads();

    // ---- per-token epilogue: softmax + top-8 (1 token/thread) ----
    {
        float* row = sc + tid * SSTR;
        float m = -3.4e38f;
        #pragma unroll
        for (int e = 0; e < NE; e++) {
            float v = row[e] + bias_s[e];
            row[e] = v;
            m = fmaxf(m, v);
        }
        float z = 0.0f;
        #pragma unroll
        for (int e = 0; e < NE; e++)
            z += exp2f((row[e] - m) * LOG2E);
        float invz = 1.0f / z;

        unsigned long long msk = 0ull;
        float tw[TOPK]; int ti[TOPK];
        float ts = 0.0f;
        #pragma unroll 1
        for (int it = 0; it < TOPK; it++) {
            float bv = -3.4e38f; int bi = 0;
            #pragma unroll
            for (int e = 0; e < NE; e++) {
                float v = row[e];
                bool ok = (((msk >> e) & 1ull) == 0ull) && (v > bv);
                if (ok) { bv = v; bi = e; }
            }
            msk |= 1ull << bi;
            float p = exp2f((bv - m) * LOG2E) * invz;
            ts += p; tw[it] = p; ti[it] = bi;
        }
        float inv = 1.0f / (ts + 1e-8f);

        const long long tok = tb + tid;
        float* ow = out + tok * TOPK;
        float* oi = out + (long long)T * TOPK + tok * TOPK;
        *(float4*)(ow)     = make_float4(tw[0]*inv, tw[1]*inv, tw[2]*inv, tw[3]*inv);
        *(float4*)(ow + 4) = make_float4(tw[4]*inv, tw[5]*inv, tw[6]*inv, tw[7]*inv);
        *(float4*)(oi)     = make_float4((float)ti[0], (float)ti[1], (float)ti[2], (float)ti[3]);
        *(float4*)(oi + 4) = make_float4((float)ti[4], (float)ti[5], (float)ti[6], (float)ti[7]);
        #pragma unroll
        for (int k = 0; k < TOPK; k++) atomicAdd(&hist_s[ti[k]], 1);
    }
    __syncthreads();

    if (tid < NE) {
        atomicAdd(&g_hist[tid], hist_s[tid]);
        __threadfence();
    }
    __syncthreads();

    // ---- last-CTA finalize ----
    if (tid == 0) {
        int t = atomicAdd(&g_cnt, 1);
        *flag_s = (t == (int)gridDim.x - 1) ? 1 : 0;
    }
    __syncthreads();
    if (*flag_s) {
        __threadfence();
        if (tid < NE) {
            int cnt = atomicAdd(&g_hist[tid], 0);
            float u = (float)cnt * inv_total;
            float* out_bias  = out + 2LL * T * TOPK;
            float* out_usage = out_bias + NE;
            out_bias[tid]  = bias_in[tid] - 0.01f * (u - 1.0f / (float)NE);
            out_usage[tid] = 0.9f * usage_in[tid] + 0.1f * u;
        }
        if (tid == 0) atomicExch(&g_cnt, 0);
    }
}

// ============================================================
extern "C" void kernel_launch(void* const* d_in, const int* in_sizes, int n_in,
                              void* d_out, int out_size) {
    const float* x     = (const float*)d_in[0];   // [4, 8192, 2048]
    const float* gw    = (const float*)d_in[1];   // [64, 2048]
    const float* bias  = (const float*)d_in[2];   // [64]
    const float* usage = (const float*)d_in[3];   // [64]

    const int T = in_sizes[0] / DIM;              // 32768
    float* out = (float*)d_out;

    const int smem_bytes = SCFL * 4 + (NE + NE) * 4 + 16;
    cudaFuncSetAttribute(gate_kernel,
                         cudaFuncAttributeMaxDynamicSharedMemorySize, smem_bytes);

    prep_kernel<<<32, 256>>>(gw);
    gate_kernel<<<T / BT, NTHR, smem_bytes>>>(x, bias, usage, out, T,
                                              1.0f / (float)(T * TOPK));
}

// round 13
// speedup vs baseline: 1.5158x; 1.0675x over previous
#include <cuda_runtime.h>
#include <stdint.h>

#define DIM   2048
#define NE    64
#define TOPK  8
#define BT    128            // tokens per CTA
#define NTHR  128
#define KC    32             // k per chunk
#define NCHK  (DIM / KC)     // 64
#define WXB   (KC * 32)      // 1024 floats: per-warp x buffer (32 tokens)
#define WWB   (KC * NE)      // 2048 floats: per-warp w buffer
#define WREG  (2 * WXB + 2 * WWB)   // 6144 floats per warp region
#define SSTR  66
#define LOG2E 1.4426950408889634f

// Transposed + bank-permuted weights [k][slot] as float4. 512 KB, L2-resident.
// Slot p of a k-row: p<8 -> experts p*8+0..3 ; p>=8 -> experts (p-8)*8+4..7.
__device__ float4 g_wt4[DIM * (NE / 4)];
__device__ int    g_hist[NE];
__device__ int    g_cnt;

// ---------------- helpers ----------------
__device__ __forceinline__ void ffma2(unsigned long long &d,
                                      unsigned long long a,
                                      unsigned long long b) {
    asm("fma.rn.f32x2 %0, %1, %2, %0;" : "+l"(d) : "l"(a), "l"(b));
}
__device__ __forceinline__ unsigned long long dup2(float w) {
    unsigned long long r;
    asm("mov.b64 %0, {%1, %1};" : "=l"(r) : "f"(w));
    return r;
}
__device__ __forceinline__ float2 ull_as_f2(unsigned long long v) {
    float2 r;
    asm("mov.b64 {%0, %1}, %2;" : "=f"(r.x), "=f"(r.y) : "l"(v));
    return r;
}
__device__ __forceinline__ void cp16(uint32_t dst_smem, const void* src) {
    asm volatile("cp.async.ca.shared.global [%0], [%1], 16;"
                 :: "r"(dst_smem), "l"(src));
}
__device__ __forceinline__ void cp_commit() {
    asm volatile("cp.async.commit_group;");
}
__device__ __forceinline__ void cp_wait0() {
    asm volatile("cp.async.wait_group 0;" ::: "memory");
}

// ============================================================
// Prep: transpose gate_weight [64][2048] -> g_wt4 [2048][16 slots]
// with the conflict-free slot permutation.
// ============================================================
__global__ void prep_kernel(const float* __restrict__ gw) {
    __shared__ float ts[64][68];
    const int t = threadIdx.x, blk = blockIdx.x;
    #pragma unroll
    for (int i = 0; i < 4; i++) {
        int idx = t + i * 256;
        int e = idx >> 4, q = idx & 15;
        float4 f = ((const float4*)gw)[e * 512 + blk * 16 + q];
        ts[e][q * 4 + 0] = f.x; ts[e][q * 4 + 1] = f.y;
        ts[e][q * 4 + 2] = f.z; ts[e][q * 4 + 3] = f.w;
    }
    __syncthreads();
    #pragma unroll
    for (int i = 0; i < 4; i++) {
        int idx = t + i * 256;
        int k = idx >> 4, p = idx & 15;
        int base = (p < 8) ? p * 8 : (p - 8) * 8 + 4;
        g_wt4[(blk * 64 + k) * 16 + p] =
            make_float4(ts[base + 0][k], ts[base + 1][k],
                        ts[base + 2][k], ts[base + 3][k]);
    }
    if (blk == 0 && t < NE) g_hist[t] = 0;
    if (blk == 0 && t == 0) g_cnt = 0;
}

// one k-step: 8 dup MOVs (alu pipe) + 32 FFMA2 (fma pipe)
#define COMPUTE_K(XA, XC, W0, W1)                                  \
    do {                                                           \
        unsigned long long wd0 = dup2((W0).x), wd1 = dup2((W0).y); \
        unsigned long long wd2 = dup2((W0).z), wd3 = dup2((W0).w); \
        unsigned long long wd4 = dup2((W1).x), wd5 = dup2((W1).y); \
        unsigned long long wd6 = dup2((W1).z), wd7 = dup2((W1).w); \
        ffma2(acc[0][0], (XA).x, wd0); ffma2(acc[1][0], (XA).y, wd0); \
        ffma2(acc[2][0], (XC).x, wd0); ffma2(acc[3][0], (XC).y, wd0); \
        ffma2(acc[0][1], (XA).x, wd1); ffma2(acc[1][1], (XA).y, wd1); \
        ffma2(acc[2][1], (XC).x, wd1); ffma2(acc[3][1], (XC).y, wd1); \
        ffma2(acc[0][2], (XA).x, wd2); ffma2(acc[1][2], (XA).y, wd2); \
        ffma2(acc[2][2], (XC).x, wd2); ffma2(acc[3][2], (XC).y, wd2); \
        ffma2(acc[0][3], (XA).x, wd3); ffma2(acc[1][3], (XA).y, wd3); \
        ffma2(acc[2][3], (XC).x, wd3); ffma2(acc[3][3], (XC).y, wd3); \
        ffma2(acc[0][4], (XA).x, wd4); ffma2(acc[1][4], (XA).y, wd4); \
        ffma2(acc[2][4], (XC).x, wd4); ffma2(acc[3][4], (XC).y, wd4); \
        ffma2(acc[0][5], (XA).x, wd5); ffma2(acc[1][5], (XA).y, wd5); \
        ffma2(acc[2][5], (XC).x, wd5); ffma2(acc[3][5], (XC).y, wd5); \
        ffma2(acc[0][6], (XA).x, wd6); ffma2(acc[1][6], (XA).y, wd6); \
        ffma2(acc[2][6], (XC).x, wd6); ffma2(acc[3][6], (XC).y, wd6); \
        ffma2(acc[0][7], (XA).x, wd7); ffma2(acc[1][7], (XA).y, wd7); \
        ffma2(acc[2][7], (XC).x, wd7); ffma2(acc[3][7], (XC).y, wd7); \
    } while (0)

// ============================================================
// Fused gate kernel. CTA: 128 tok x 64 exp, 128 threads; grid 256.
// Each warp owns 32 tokens with PRIVATE double-buffered x and w
// smem — the mainloop has NO __syncthreads (warp-synchronous).
// Thread tile 8 tok x 8 exp. Per-(token,expert): sequential fp32
// FMA chain, k ascending — bitwise identical to R1/R6-R12.
// ============================================================
__global__ void __launch_bounds__(NTHR, 2)
gate_kernel(const float* __restrict__ x,
            const float* __restrict__ bias_in,
            const float* __restrict__ usage_in,
            float* __restrict__ out, int T, float inv_total) {
    extern __shared__ float sm[];
    // per-warp regions: [warp][2x1024 x | 2x2048 w]; scores alias region.
    float* sc     = sm;                        // [128][66] = 8448 f (alias)
    float* bias_s = sm + 4 * WREG;             // [64]
    int*   hist_s = (int*)(bias_s + NE);       // [64]
    int*   flag_s = hist_s + NE;

    const int tid  = threadIdx.x;
    const int wid  = tid >> 5;
    const int lane = tid & 31;
    const int tgl  = lane >> 3;                // local token group (0..3)
    const int eg   = lane & 7;                 // expert group
    const long long tb = (long long)blockIdx.x * BT;

    if (tid < NE) { hist_s[tid] = 0; bias_s[tid] = bias_in[tid]; }

    float* xw = sm + wid * WREG;               // [2][KC][32]
    float* ww = xw + 2 * WXB;                  // [2][KC][64]
    const uint32_t ww_u32 = (uint32_t)__cvta_generic_to_shared(ww);
    const float* xg = x + (tb + wid * 32 + lane) * (long long)DIM;

    // ---- stage chunk 0 (warp-local) ----
    {
        #pragma unroll
        for (int j = 0; j < 8; j++) {
            float4 v = *(const float4*)(xg + j * 4);
            xw[(j * 4 + 0) * 32 + lane] = v.x;
            xw[(j * 4 + 1) * 32 + lane] = v.y;
            xw[(j * 4 + 2) * 32 + lane] = v.z;
            xw[(j * 4 + 3) * 32 + lane] = v.w;
        }
        #pragma unroll
        for (int i = 0; i < 16; i++)
            cp16(ww_u32 + (lane + i * 32) * 16, &g_wt4[lane + i * 32]);
        cp_commit();
    }

    unsigned long long acc[4][8];
    #pragma unroll
    for (int tp = 0; tp < 4; tp++)
        #pragma unroll
        for (int e = 0; e < 8; e++) acc[tp][e] = 0ull;

    cp_wait0();
    __syncwarp();

    for (int ch = 0; ch < NCHK; ch++) {
        const int buf = ch & 1;

        // next-chunk producers (warp-local): x to regs, w via cp.async
        float4 xr[8];
        if (ch + 1 < NCHK) {
            const float* xp = xg + (ch + 1) * KC;
            #pragma unroll
            for (int j = 0; j < 8; j++)
                xr[j] = *(const float4*)(xp + j * 4);
            const uint32_t wdst = ww_u32 + (buf ^ 1) * (WWB * 4);
            const float4* wsrc = &g_wt4[(ch + 1) * 512];
            #pragma unroll
            for (int i = 0; i < 16; i++)
                cp16(wdst + (lane + i * 32) * 16, wsrc + lane + i * 32);
            cp_commit();
        }

        const float* xb = xw + buf * WXB + tgl * 8;
        const float* wb = ww + buf * WWB + eg * 4;   // permuted, conflict-free

        // software-pipelined inner loop: 1-k operand double buffer
        ulonglong2 xa = *(const ulonglong2*)(xb);
        ulonglong2 xc = *(const ulonglong2*)(xb + 4);
        float4 w0 = *(const float4*)(wb);
        float4 w1 = *(const float4*)(wb + 32);

        #pragma unroll
        for (int k = 0; k < KC - 1; k++) {
            ulonglong2 xa2 = *(const ulonglong2*)(xb + (k + 1) * 32);
            ulonglong2 xc2 = *(const ulonglong2*)(xb + (k + 1) * 32 + 4);
            float4 v0 = *(const float4*)(wb + (k + 1) * NE);
            float4 v1 = *(const float4*)(wb + (k + 1) * NE + 32);
            COMPUTE_K(xa, xc, w0, w1);
            xa = xa2; xc = xc2; w0 = v0; w1 = v1;
        }
        COMPUTE_K(xa, xc, w0, w1);   // peeled last k

        // stage next x chunk (warp-local STS transpose)
        if (ch + 1 < NCHK) {
            float* xd = xw + (buf ^ 1) * WXB;
            #pragma unroll
            for (int j = 0; j < 8; j++) {
                xd[(j * 4 + 0) * 32 + lane] = xr[j].x;
                xd[(j * 4 + 1) * 32 + lane] = xr[j].y;
                xd[(j * 4 + 2) * 32 + lane] = xr[j].z;
                xd[(j * 4 + 3) * 32 + lane] = xr[j].w;
            }
            cp_wait0();
        }
        __syncwarp();
    }

    __syncthreads();   // all warps done; pipeline regions become score space

    // ---- accumulators -> smem scores ----
    #pragma unroll
    for (int tp = 0; tp < 4; tp++) {
        #pragma unroll
        for (int e = 0; e < 8; e++) {
            float2 v = ull_as_f2(acc[tp][e]);
            const int row = wid * 32 + tgl * 8 + tp * 2;
            sc[row * SSTR + eg * 8 + e]       = v.x;
            sc[(row + 1) * SSTR + eg * 8 + e] = v.y;
        }
    }
    __syncthreads();

    // ---- per-token epilogue: softmax + top-8 (1 token/thread) ----
    {
        float* row = sc + tid * SSTR;
        float m = -3.4e38f;
        #pragma unroll
        for (int e = 0; e < NE; e++) {
            float v = row[e] + bias_s[e];
            row[e] = v;
            m = fmaxf(m, v);
        }
        float z = 0.0f;
        #pragma unroll
        for (int e = 0; e < NE; e++)
            z += exp2f((row[e] - m) * LOG2E);
        float invz = 1.0f / z;

        unsigned long long msk = 0ull;
        float tw[TOPK]; int ti[TOPK];
        float ts = 0.0f;
        #pragma unroll 1
        for (int it = 0; it < TOPK; it++) {
            float bv = -3.4e38f; int bi = 0;
            #pragma unroll
            for (int e = 0; e < NE; e++) {
                float v = row[e];
                bool ok = (((msk >> e) & 1ull) == 0ull) && (v > bv);
                if (ok) { bv = v; bi = e; }
            }
            msk |= 1ull << bi;
            float p = exp2f((bv - m) * LOG2E) * invz;
            ts += p; tw[it] = p; ti[it] = bi;
        }
        float inv = 1.0f / (ts + 1e-8f);

        const long long tok = tb + tid;
        float* ow = out + tok * TOPK;
        float* oi = out + (long long)T * TOPK + tok * TOPK;
        *(float4*)(ow)     = make_float4(tw[0]*inv, tw[1]*inv, tw[2]*inv, tw[3]*inv);
        *(float4*)(ow + 4) = make_float4(tw[4]*inv, tw[5]*inv, tw[6]*inv, tw[7]*inv);
        *(float4*)(oi)     = make_float4((float)ti[0], (float)ti[1], (float)ti[2], (float)ti[3]);
        *(float4*)(oi + 4) = make_float4((float)ti[4], (float)ti[5], (float)ti[6], (float)ti[7]);
        #pragma unroll
        for (int k = 0; k < TOPK; k++) atomicAdd(&hist_s[ti[k]], 1);
    }
    __syncthreads();

    if (tid < NE) {
        atomicAdd(&g_hist[tid], hist_s[tid]);
        __threadfence();
    }
    __syncthreads();

    // ---- last-CTA finalize ----
    if (tid == 0) {
        int t = atomicAdd(&g_cnt, 1);
        *flag_s = (t == (int)gridDim.x - 1) ? 1 : 0;
    }
    __syncthreads();
    if (*flag_s) {
        __threadfence();
        if (tid < NE) {
            int cnt = atomicAdd(&g_hist[tid], 0);
            float u = (float)cnt * inv_total;
            float* out_bias  = out + 2LL * T * TOPK;
            float* out_usage = out_bias + NE;
            out_bias[tid]  = bias_in[tid] - 0.01f * (u - 1.0f / (float)NE);
            out_usage[tid] = 0.9f * usage_in[tid] + 0.1f * u;
        }
        if (tid == 0) atomicExch(&g_cnt, 0);
    }
}

// ============================================================
extern "C" void kernel_launch(void* const* d_in, const int* in_sizes, int n_in,
                              void* d_out, int out_size) {
    const float* x     = (const float*)d_in[0];   // [4, 8192, 2048]
    const float* gw    = (const float*)d_in[1];   // [64, 2048]
    const float* bias  = (const float*)d_in[2];   // [64]
    const float* usage = (const float*)d_in[3];   // [64]

    const int T = in_sizes[0] / DIM;              // 32768
    float* out = (float*)d_out;

    const int smem_bytes = (4 * WREG + NE) * 4 + NE * 4 + 16;
    cudaFuncSetAttribute(gate_kernel,
                         cudaFuncAttributeMaxDynamicSharedMemorySize, smem_bytes);

    prep_kernel<<<32, 256>>>(gw);
    gate_kernel<<<T / BT, NTHR, smem_bytes>>>(x, bias, usage, out, T,
                                              1.0f / (float)(T * TOPK));
}